// round 10
// baseline (speedup 1.0000x reference)
#include <cuda_runtime.h>
#include <math.h>

// ---------------- problem constants ----------------
#define N8   130560   // (2176/8)*(3840/8)
#define N16  32640
#define N32  8160
#define NT   (N8 + N16 + N32)   // 171360
#define N8_4  (N8 / 4)
#define N16_4 (N16 / 4)
#define NT4   (NT / 4)
#define FW8  480
#define FW16 240
#define FW32 120
#define TOPK 1000
#define NCAND 4096
#define NBINS 4096
#define HICAP 16384
#define NMS_T 0.4f

#define GRID1 148
#define BLK   512
#define NTH1  (GRID1 * BLK)
#define GRID2 32
#define NTH2  (GRID2 * BLK)      // 16384
#define NW2   (NTH2 / 32)        // 512

#define BIN_BASE    0x1FC00u     // 0x3F800000 >> 13  (raw == 1.0f)
#define COARSE_BITS 0x40000000u  // raw == 2.0f

// ---------------- device scratch (no allocations allowed) ----------------
__device__ unsigned int        g_hist[NBINS];     // zero at load; re-zeroed every run
__device__ unsigned int        g_hicount;         // zero at load; reset every run
__device__ unsigned long long  g_hi[HICAP];
__device__ unsigned int        g_ccount;          // zero at load; reset every run
__device__ unsigned long long  g_cand[NCAND];
__device__ float4              g_bx4[1024];
__device__ float               g_sc[1024];
__device__ float               g_kp[1024 * 10];
__device__ int                 g_val[1024];
__device__ unsigned int        g_mask[1024 * 32];
__device__ unsigned int        g_nzchunks;
// software barriers (generation/count based; self-resetting across replays)
__device__ unsigned int           g_bar_count;
__device__ volatile unsigned int  g_bar_gen;
__device__ unsigned int           g_done;

__device__ __forceinline__ void grid_sync2() {   // GRID2-wide
    __syncthreads();
    if (threadIdx.x == 0) {
        __threadfence();
        unsigned int gen = g_bar_gen;
        if (atomicAdd(&g_bar_count, 1u) == GRID2 - 1) {
            g_bar_count = 0;
            __threadfence();
            g_bar_gen = gen + 1;
        } else {
            while (g_bar_gen == gen) { }
        }
        __threadfence();
    }
    __syncthreads();
}

// monotone bin for positive raw-score bits
__device__ __forceinline__ unsigned int raw_bin(unsigned int bits) {
    return (bits >= 0x3F800000u) ? min(4095u, (bits >> 13) - BIN_BASE) : 0u;
}

__device__ __forceinline__ void front_elem(float raw, unsigned int idx) {
    if (raw > 0.0f) {
        unsigned int bits = __float_as_uint(raw);
        atomicAdd(&g_hist[raw_bin(bits)], 1u);
        if (bits >= COARSE_BITS) {
            unsigned int pos = atomicAdd(&g_hicount, 1u);
            if (pos < HICAP)
                g_hi[pos] = ((unsigned long long)bits << 32) |
                            (unsigned long long)(0xFFFFFFFFu - idx);
        }
    }
}

// ================= K1: raw-bits histogram + coarse candidate store =================
__global__ __launch_bounds__(BLK)
void k_front(const float* __restrict__ s8, const float* __restrict__ s16,
             const float* __restrict__ s32) {
    const int tid = blockIdx.x * BLK + threadIdx.x;
    for (int v = tid; v < NT4; v += NTH1) {
        float4 r;
        if (v < N8_4)               r = reinterpret_cast<const float4*>(s8)[v];
        else if (v < N8_4 + N16_4)  r = reinterpret_cast<const float4*>(s16)[v - N8_4];
        else                        r = reinterpret_cast<const float4*>(s32)[v - N8_4 - N16_4];
        unsigned int base = (unsigned int)v * 4u;
        front_elem(r.x, base);
        front_elem(r.y, base + 1u);
        front_elem(r.z, base + 2u);
        front_elem(r.w, base + 3u);
    }
}

// ===== K2 (32 blocks): kmin -> compact -> rank+decode -> mask -> reduce -> out =====
__global__ __launch_bounds__(BLK)
void k_rest(const float* __restrict__ s8,  const float* __restrict__ s16, const float* __restrict__ s32,
            const float* __restrict__ b8,  const float* __restrict__ k8,
            const float* __restrict__ b16, const float* __restrict__ k16,
            const float* __restrict__ b32, const float* __restrict__ k32,
            float* __restrict__ out) {
    const int tid  = blockIdx.x * BLK + threadIdx.x;
    const int t    = threadIdx.x;
    const int lane = t & 31;
    const int w    = t >> 5;

    // ---- B: per-block redundant boundary-bin search over raw-bit histogram ----
    __shared__ unsigned int sw_tot[BLK / 32];
    __shared__ unsigned int skmin;
    unsigned int kmin;
    {
        unsigned int loc[8];
        unsigned int p = 0;
        #pragma unroll
        for (int b = 0; b < 8; b++) { loc[b] = g_hist[t * 8 + b]; p += loc[b]; }
        unsigned int s = p;   // warp suffix-sum over lanes >= lane
        #pragma unroll
        for (int d = 1; d < 32; d <<= 1) {
            unsigned int o = __shfl_down_sync(0xFFFFFFFFu, s, d);
            if (lane + d < 32) s += o;
        }
        unsigned int wtot = __shfl_sync(0xFFFFFFFFu, s, 0);
        if (lane == 0) sw_tot[w] = wtot;
        __syncthreads();
        unsigned int tail = 0;
        #pragma unroll
        for (int ww = 0; ww < BLK / 32; ww++) tail += (ww > w) ? sw_tot[ww] : 0u;
        unsigned int suffix = s + tail;     // sum of bins [t*8 .. NBINS)
        unsigned int nxt = suffix - p;
        if (suffix >= TOPK && nxt < TOPK) {
            unsigned int running = nxt;
            int B = t * 8;
            #pragma unroll
            for (int b = 7; b >= 0; b--) {
                running += loc[b];
                if (running >= TOPK) { B = t * 8 + b; break; }
            }
            skmin = (B == 0) ? 1u : (((unsigned int)B + BIN_BASE) << 13);
        }
        if (t == 0 && suffix < TOPK) skmin = 1u;   // fewer than TOPK valid overall
        __syncthreads();
        kmin = skmin;
    }

    // ---- C: collect candidates >= kmin ----
    unsigned int hic = g_hicount;
    bool fallback = (kmin < COARSE_BITS) || (hic > HICAP);
    if (!fallback) {
        // fast path: compact the coarse store (covers every key >= kmin >= COARSE)
        for (unsigned int e = tid; e < hic; e += NTH2) {
            unsigned long long pk = g_hi[e];
            if ((unsigned int)(pk >> 32) >= kmin) {
                unsigned int pos = atomicAdd(&g_ccount, 1u);
                if (pos < NCAND) g_cand[pos] = pk;
            }
        }
    } else {
        // correctness fallback: full rescan
        for (int v = tid; v < NT4; v += NTH2) {
            float4 r;
            if (v < N8_4)               r = reinterpret_cast<const float4*>(s8)[v];
            else if (v < N8_4 + N16_4)  r = reinterpret_cast<const float4*>(s16)[v - N8_4];
            else                        r = reinterpret_cast<const float4*>(s32)[v - N8_4 - N16_4];
            float  ra[4] = {r.x, r.y, r.z, r.w};
            unsigned int base = (unsigned int)v * 4u;
            #pragma unroll
            for (int c = 0; c < 4; c++) {
                if (ra[c] > 0.0f) {
                    unsigned int bits = __float_as_uint(ra[c]);
                    if (bits >= kmin) {
                        unsigned int pos = atomicAdd(&g_ccount, 1u);
                        if (pos < NCAND)
                            g_cand[pos] = ((unsigned long long)bits << 32) |
                                          (unsigned long long)(0xFFFFFFFFu - (base + c));
                    }
                }
            }
        }
    }
    grid_sync2();

    // ---- DE: warp-per-candidate exact rank + direct decode ----
    {
        unsigned int C = g_ccount;
        if (C > NCAND) C = NCAND;

        // housekeeping for next replay / this run
        for (int i = tid; i < NBINS; i += NTH2) g_hist[i] = 0;
        if (tid == 0) { g_hicount = 0; g_nzchunks = 0u; }

        // zero never-written rank rows [C, 1024)
        if (tid >= (int)C && tid < 1024) {
            g_val[tid] = 0;
            g_sc[tid] = 0.0f;
            g_bx4[tid] = make_float4(0.0f, 0.0f, 0.0f, 0.0f);
            #pragma unroll
            for (int c = 0; c < 10; c++) g_kp[tid * 10 + c] = 0.0f;
        }

        int gw = tid >> 5;
        for (int cand = gw; cand < (int)C; cand += NW2) {
            unsigned long long mine = g_cand[cand];
            int cnt = 0;
            for (int i = lane; i < (int)C; i += 32) cnt += (g_cand[i] > mine) ? 1 : 0;
            int rank = __reduce_add_sync(0xFFFFFFFFu, cnt);
            if (rank < TOPK && lane == 0) {
                unsigned int bits = (unsigned int)(mine >> 32);
                float raw = __uint_as_float(bits);
                int idx = (int)(0xFFFFFFFFu - (unsigned int)(mine & 0xFFFFFFFFu));
                int li, fw;
                float stride;
                const float* bb;
                const float* kp;
                if (idx < N8)            { li = idx;            stride = 8.0f;  fw = FW8;  bb = b8;  kp = k8;  }
                else if (idx < N8 + N16) { li = idx - N8;       stride = 16.0f; fw = FW16; bb = b16; kp = k16; }
                else                     { li = idx - N8 - N16; stride = 32.0f; fw = FW32; bb = b32; kp = k32; }
                float cx = (float)(li % fw) * stride;
                float cy = (float)(li / fw) * stride;
                float4 d = reinterpret_cast<const float4*>(bb)[li];
                g_bx4[rank] = make_float4(cx - d.x * stride, cy - d.y * stride,
                                          cx + d.z * stride, cy + d.w * stride);
                const float2* kk2 = reinterpret_cast<const float2*>(kp) + (size_t)li * 5;
                #pragma unroll
                for (int j = 0; j < 5; j++) {
                    float2 kv = kk2[j];
                    g_kp[rank * 10 + 2 * j]     = kv.x * stride + cx;
                    g_kp[rank * 10 + 2 * j + 1] = kv.y * stride + cy;
                }
                g_sc[rank] = 1.0f / (1.0f + expf(-raw));
                g_val[rank] = 1;
            }
        }
    }
    grid_sync2();

    // ---- F: upper-triangle suppression bitmask only ----
    if (tid == 0) g_ccount = 0;   // consumed; reset for next replay
    {
        int gw = tid >> 5;
        for (int task = gw; task < TOPK * 32; task += NW2) {
            int i  = task >> 5;
            int wj = task & 31;
            if (wj * 32 + 31 <= i) continue;    // word entirely j <= i: G masks it
            float4 bi = g_bx4[i];
            int j = wj * 32 + lane;
            float4 bj = g_bx4[j];
            bool bit = false;
            if (j < TOPK && j > i) {
                float iar = (bi.z - bi.x) * (bi.w - bi.y);
                float jar = (bj.z - bj.x) * (bj.w - bj.y);
                float ww2 = fmaxf(fminf(bi.z, bj.z) - fmaxf(bi.x, bj.x), 0.0f);
                float hh2 = fmaxf(fminf(bi.w, bj.w) - fmaxf(bi.y, bj.y), 0.0f);
                float inter = ww2 * hh2;
                float uni = fmaxf(iar + jar - inter, 1e-9f);
                bit = inter > NMS_T * uni;
            }
            unsigned int b = __ballot_sync(0xFFFFFFFFu, bit);
            if (lane == 0) {
                g_mask[i * 32 + wj] = b;
                if (b) atomicOr(&g_nzchunks, 1u << (i >> 5));
            }
        }
    }

    // ---- arrive-and-exit: only block 0 proceeds to G ----
    __syncthreads();
    if (threadIdx.x == 0) { __threadfence(); atomicAdd(&g_done, 1u); }
    if (blockIdx.x != 0) return;
    if (threadIdx.x == 0) {
        while (*(volatile unsigned int*)&g_done != GRID2) { }
        g_done = 0;
        __threadfence();
    }
    __syncthreads();

    // ---- G: greedy reduce over nonzero chunks + outputs (block 0 only) ----
    {
        __shared__ unsigned int svalid[32];
        __shared__ unsigned int srem[32];
        for (int c = w; c < 32; c += BLK / 32) {
            int idx = c * 32 + lane;
            int v = (idx < TOPK) ? g_val[idx] : 0;
            unsigned int b = __ballot_sync(0xFFFFFFFFu, v != 0);
            if (lane == 0) svalid[c] = b;
        }
        __syncthreads();

        if (t < 32) {
            unsigned int rem = 0;
            unsigned int nz = g_nzchunks;    // uniform across lanes
            while (nz) {
                int c = __ffs(nz) - 1;       // ascending chunk order
                nz &= nz - 1;
                unsigned int m[32];
                #pragma unroll
                for (int k = 0; k < 32; k++) {
                    unsigned int mm = g_mask[(c * 32 + k) * 32 + lane];
                    // validity: word covers j in [32*lane, 32*lane+31]; need j > row=32c+k
                    unsigned int vmask;
                    if (lane > c)       vmask = 0xFFFFFFFFu;
                    else if (lane < c)  vmask = 0u;
                    else                vmask = (k == 31) ? 0u : (0xFFFFFFFFu << (k + 1));
                    m[k] = mm & vmask;
                }
                unsigned int vb = svalid[c];
                unsigned int myrem = rem;
                unsigned int kb = 0;
                #pragma unroll
                for (int k2 = 0; k2 < 32; k2++) {
                    unsigned int kept = ((vb >> k2) & 1u) & ((~(myrem >> k2)) & 1u);
                    kb |= kept << k2;
                    myrem |= (0u - kept) & m[k2];
                }
                unsigned int keptbits = __shfl_sync(0xFFFFFFFFu, kb, c);
                #pragma unroll
                for (int k2 = 0; k2 < 32; k2++)
                    rem |= (0u - ((keptbits >> k2) & 1u)) & m[k2];
            }
            srem[lane] = rem;
        }
        __syncthreads();

        // outputs: [boxes 1000*4 | scores 1000 | kpss 1000*10] = 15000 floats
        for (int r = t; r < TOPK; r += BLK) {
            unsigned int rw = srem[r >> 5];
            int keep = g_val[r] && !((rw >> (r & 31)) & 1u);
            float m = keep ? 1.0f : 0.0f;
            float4 b = g_bx4[r];
            out[r * 4 + 0] = m * b.x;
            out[r * 4 + 1] = m * b.y;
            out[r * 4 + 2] = m * b.z;
            out[r * 4 + 3] = m * b.w;
            out[4000 + r] = m * g_sc[r];
            #pragma unroll
            for (int c = 0; c < 10; c++)
                out[5000 + r * 10 + c] = m * g_kp[r * 10 + c];
        }
    }
}

// ---------------- launcher: 2 graph nodes ----------------
extern "C" void kernel_launch(void* const* d_in, const int* in_sizes, int n_in,
                              void* d_out, int out_size) {
    // metadata order: x, scores8, bbox8, kps8, scores16, bbox16, kps16, scores32, bbox32, kps32
    const float* s8  = (const float*)d_in[1];
    const float* b8  = (const float*)d_in[2];
    const float* k8  = (const float*)d_in[3];
    const float* s16 = (const float*)d_in[4];
    const float* b16 = (const float*)d_in[5];
    const float* k16 = (const float*)d_in[6];
    const float* s32 = (const float*)d_in[7];
    const float* b32 = (const float*)d_in[8];
    const float* k32 = (const float*)d_in[9];
    float* out = (float*)d_out;

    k_front<<<GRID1, BLK>>>(s8, s16, s32);
    k_rest<<<GRID2, BLK>>>(s8, s16, s32, b8, k8, b16, k16, b32, k32, out);
}

// round 11
// speedup vs baseline: 2.1361x; 2.1361x over previous
#include <cuda_runtime.h>
#include <math.h>

// ---------------- problem constants ----------------
#define N8   130560   // (2176/8)*(3840/8)
#define N16  32640
#define N32  8160
#define NT   (N8 + N16 + N32)   // 171360
#define N8_4  (N8 / 4)
#define N16_4 (N16 / 4)
#define NT4   (NT / 4)
#define FW8  480
#define FW16 240
#define FW32 120
#define TOPK 1000
#define NCAND 4096
#define NBINS 4096
#define HICAP 16384
#define NMS_T 0.4f

#define GRID1 148
#define BLK   512
#define NTH1  (GRID1 * BLK)
#define GRID2 32
#define NTH2  (GRID2 * BLK)      // 16384
#define NW2   (NTH2 / 32)        // 512

#define BIN_BASE    0x1FC00u     // 0x3F800000 >> 13  (raw == 1.0f)
#define COARSE_BITS 0x40000000u  // raw == 2.0f

// ---------------- device scratch (no allocations allowed) ----------------
__device__ unsigned int        g_hist[NBINS];     // zero at load; re-zeroed every run
__device__ unsigned int        g_hicount;         // zero at load; reset every run
__device__ unsigned long long  g_hi[HICAP];
__device__ unsigned int        g_ccount;          // zero at load; reset every run
__device__ unsigned long long  g_cand[NCAND];
__device__ float4              g_bx4[1024];
__device__ float               g_sc[1024];
__device__ float               g_kp[1024 * 10];
__device__ int                 g_val[1024];
__device__ unsigned int        g_mask[1024 * 32];
__device__ unsigned int        g_nzchunks;
// software barriers (generation/count based; self-resetting across replays)
__device__ unsigned int           g_bar_count;
__device__ volatile unsigned int  g_bar_gen;
__device__ unsigned int           g_done;

__device__ __forceinline__ void grid_sync2() {   // GRID2-wide
    __syncthreads();
    if (threadIdx.x == 0) {
        __threadfence();
        unsigned int gen = g_bar_gen;
        if (atomicAdd(&g_bar_count, 1u) == GRID2 - 1) {
            g_bar_count = 0;
            __threadfence();
            g_bar_gen = gen + 1;
        } else {
            while (g_bar_gen == gen) { }
        }
        __threadfence();
    }
    __syncthreads();
}

// spread bin for bits >= 1.0f: bins 1..4095;  bin 0 = positives below 1.0f
__device__ __forceinline__ unsigned int hi_bin(unsigned int bits) {
    return min(4095u, (bits >> 13) - BIN_BASE + 1u);
}

// ================= K1: histogram (de-contended) + coarse candidate store =================
__global__ __launch_bounds__(BLK)
void k_front(const float* __restrict__ s8, const float* __restrict__ s16,
             const float* __restrict__ s32) {
    const int tid = blockIdx.x * BLK + threadIdx.x;
    for (int v = tid; v < NT4; v += NTH1) {
        float4 r;
        if (v < N8_4)               r = reinterpret_cast<const float4*>(s8)[v];
        else if (v < N8_4 + N16_4)  r = reinterpret_cast<const float4*>(s16)[v - N8_4];
        else                        r = reinterpret_cast<const float4*>(s32)[v - N8_4 - N16_4];
        float ra[4] = {r.x, r.y, r.z, r.w};
        unsigned int base = (unsigned int)v * 4u;
        int c0 = 0;   // positives below 1.0 (bin-0 aggregate)
        #pragma unroll
        for (int c = 0; c < 4; c++) {
            float raw = ra[c];
            if (raw >= 1.0f) {
                unsigned int bits = __float_as_uint(raw);
                atomicAdd(&g_hist[hi_bin(bits)], 1u);
                if (bits >= COARSE_BITS) {
                    unsigned int pos = atomicAdd(&g_hicount, 1u);
                    if (pos < HICAP)
                        g_hi[pos] = ((unsigned long long)bits << 32) |
                                    (unsigned long long)(0xFFFFFFFFu - (base + c));
                }
            } else if (raw > 0.0f) {
                c0++;
            }
        }
        // warp-aggregated bin-0 update (converged active lanes)
        unsigned int act = __activemask();
        int tot = c0;
        #pragma unroll
        for (int d = 16; d > 0; d >>= 1) tot += __shfl_xor_sync(act, tot, d);
        if ((threadIdx.x & 31) == (unsigned)(__ffs(act) - 1) && tot > 0)
            atomicAdd(&g_hist[0], (unsigned int)tot);
    }
}

// ===== K2 (32 blocks): kmin -> compact -> rank+decode -> mask -> reduce -> out =====
__global__ __launch_bounds__(BLK)
void k_rest(const float* __restrict__ s8,  const float* __restrict__ s16, const float* __restrict__ s32,
            const float* __restrict__ b8,  const float* __restrict__ k8,
            const float* __restrict__ b16, const float* __restrict__ k16,
            const float* __restrict__ b32, const float* __restrict__ k32,
            float* __restrict__ out) {
    const int tid  = blockIdx.x * BLK + threadIdx.x;
    const int t    = threadIdx.x;
    const int lane = t & 31;
    const int w    = t >> 5;

    __shared__ unsigned long long scand[NCAND];   // 32 KB candidate stage
    __shared__ float4             sbx[1024];      // 16 KB box stage

    // ---- B: per-block redundant boundary-bin search ----
    __shared__ unsigned int sw_tot[BLK / 32];
    __shared__ unsigned int skmin;
    unsigned int kmin;
    {
        unsigned int loc[8];
        unsigned int p = 0;
        #pragma unroll
        for (int b = 0; b < 8; b++) { loc[b] = g_hist[t * 8 + b]; p += loc[b]; }
        unsigned int s = p;   // warp suffix-sum over lanes >= lane
        #pragma unroll
        for (int d = 1; d < 32; d <<= 1) {
            unsigned int o = __shfl_down_sync(0xFFFFFFFFu, s, d);
            if (lane + d < 32) s += o;
        }
        unsigned int wtot = __shfl_sync(0xFFFFFFFFu, s, 0);
        if (lane == 0) sw_tot[w] = wtot;
        __syncthreads();
        unsigned int tail = 0;
        #pragma unroll
        for (int ww = 0; ww < BLK / 32; ww++) tail += (ww > w) ? sw_tot[ww] : 0u;
        unsigned int suffix = s + tail;     // sum of bins [t*8 .. NBINS)
        unsigned int nxt = suffix - p;
        if (suffix >= TOPK && nxt < TOPK) {
            unsigned int running = nxt;
            int B = t * 8;
            #pragma unroll
            for (int b = 7; b >= 0; b--) {
                running += loc[b];
                if (running >= TOPK) { B = t * 8 + b; break; }
            }
            skmin = (B == 0) ? 1u : ((BIN_BASE + (unsigned int)B - 1u) << 13);
        }
        if (t == 0 && suffix < TOPK) skmin = 1u;   // fewer than TOPK valid overall
        __syncthreads();
        kmin = skmin;
    }

    // ---- C: collect candidates >= kmin ----
    unsigned int hic = g_hicount;
    bool fallback = (kmin < COARSE_BITS) || (hic > HICAP);
    if (!fallback) {
        for (unsigned int e = tid; e < hic; e += NTH2) {
            unsigned long long pk = g_hi[e];
            if ((unsigned int)(pk >> 32) >= kmin) {
                unsigned int pos = atomicAdd(&g_ccount, 1u);
                if (pos < NCAND) g_cand[pos] = pk;
            }
        }
    } else {
        for (int v = tid; v < NT4; v += NTH2) {
            float4 r;
            if (v < N8_4)               r = reinterpret_cast<const float4*>(s8)[v];
            else if (v < N8_4 + N16_4)  r = reinterpret_cast<const float4*>(s16)[v - N8_4];
            else                        r = reinterpret_cast<const float4*>(s32)[v - N8_4 - N16_4];
            float  ra[4] = {r.x, r.y, r.z, r.w};
            unsigned int base = (unsigned int)v * 4u;
            #pragma unroll
            for (int c = 0; c < 4; c++) {
                if (ra[c] > 0.0f) {
                    unsigned int bits = __float_as_uint(ra[c]);
                    if (bits >= kmin) {
                        unsigned int pos = atomicAdd(&g_ccount, 1u);
                        if (pos < NCAND)
                            g_cand[pos] = ((unsigned long long)bits << 32) |
                                          (unsigned long long)(0xFFFFFFFFu - (base + c));
                    }
                }
            }
        }
    }
    grid_sync2();

    // ---- DE: stage candidates in smem; warp-per-candidate rank + decode ----
    {
        unsigned int C = g_ccount;
        if (C > NCAND) C = NCAND;

        for (unsigned int i = t; i < C; i += BLK) scand[i] = g_cand[i];

        // housekeeping for next replay / this run
        for (int i = tid; i < NBINS; i += NTH2) g_hist[i] = 0;
        if (tid == 0) { g_hicount = 0; g_nzchunks = 0u; }

        // zero never-written rank rows [C, 1024)
        if (tid >= (int)C && tid < 1024) {
            g_val[tid] = 0;
            g_sc[tid] = 0.0f;
            g_bx4[tid] = make_float4(0.0f, 0.0f, 0.0f, 0.0f);
            #pragma unroll
            for (int c = 0; c < 10; c++) g_kp[tid * 10 + c] = 0.0f;
        }
        __syncthreads();

        int gw = tid >> 5;
        for (int cand = gw; cand < (int)C; cand += NW2) {
            unsigned long long mine = scand[cand];
            int cnt = 0;
            for (int i = lane; i < (int)C; i += 32) cnt += (scand[i] > mine) ? 1 : 0;
            int rank = __reduce_add_sync(0xFFFFFFFFu, cnt);
            if (rank < TOPK && lane == 0) {
                unsigned int bits = (unsigned int)(mine >> 32);
                float raw = __uint_as_float(bits);
                int idx = (int)(0xFFFFFFFFu - (unsigned int)(mine & 0xFFFFFFFFu));
                int li, fw;
                float stride;
                const float* bb;
                const float* kp;
                if (idx < N8)            { li = idx;            stride = 8.0f;  fw = FW8;  bb = b8;  kp = k8;  }
                else if (idx < N8 + N16) { li = idx - N8;       stride = 16.0f; fw = FW16; bb = b16; kp = k16; }
                else                     { li = idx - N8 - N16; stride = 32.0f; fw = FW32; bb = b32; kp = k32; }
                float cx = (float)(li % fw) * stride;
                float cy = (float)(li / fw) * stride;
                float4 d = reinterpret_cast<const float4*>(bb)[li];
                g_bx4[rank] = make_float4(cx - d.x * stride, cy - d.y * stride,
                                          cx + d.z * stride, cy + d.w * stride);
                const float2* kk2 = reinterpret_cast<const float2*>(kp) + (size_t)li * 5;
                #pragma unroll
                for (int j = 0; j < 5; j++) {
                    float2 kv = kk2[j];
                    g_kp[rank * 10 + 2 * j]     = kv.x * stride + cx;
                    g_kp[rank * 10 + 2 * j + 1] = kv.y * stride + cy;
                }
                g_sc[rank] = 1.0f / (1.0f + expf(-raw));
                g_val[rank] = 1;
            }
        }
    }
    grid_sync2();

    // ---- F: stage boxes in smem; upper-triangle suppression bitmask ----
    if (tid == 0) g_ccount = 0;   // consumed; reset for next replay
    {
        for (int i = t; i < 1024; i += BLK) sbx[i] = g_bx4[i];
        __syncthreads();

        int gw = tid >> 5;
        for (int task = gw; task < TOPK * 32; task += NW2) {
            int i  = task >> 5;
            int wj = task & 31;
            if (wj * 32 + 31 <= i) continue;    // word entirely j <= i: G masks it
            float4 bi = sbx[i];
            int j = wj * 32 + lane;
            float4 bj = sbx[j];
            bool bit = false;
            if (j < TOPK && j > i) {
                float iar = (bi.z - bi.x) * (bi.w - bi.y);
                float jar = (bj.z - bj.x) * (bj.w - bj.y);
                float ww2 = fmaxf(fminf(bi.z, bj.z) - fmaxf(bi.x, bj.x), 0.0f);
                float hh2 = fmaxf(fminf(bi.w, bj.w) - fmaxf(bi.y, bj.y), 0.0f);
                float inter = ww2 * hh2;
                float uni = fmaxf(iar + jar - inter, 1e-9f);
                bit = inter > NMS_T * uni;
            }
            unsigned int b = __ballot_sync(0xFFFFFFFFu, bit);
            if (lane == 0) {
                g_mask[i * 32 + wj] = b;
                if (b) atomicOr(&g_nzchunks, 1u << (i >> 5));
            }
        }
    }

    // ---- arrive-and-exit: only block 0 proceeds to G ----
    __syncthreads();
    if (threadIdx.x == 0) { __threadfence(); atomicAdd(&g_done, 1u); }
    if (blockIdx.x != 0) return;
    if (threadIdx.x == 0) {
        while (*(volatile unsigned int*)&g_done != GRID2) { }
        g_done = 0;
        __threadfence();
    }
    __syncthreads();

    // ---- G: greedy reduce over nonzero chunks + outputs (block 0 only) ----
    {
        __shared__ unsigned int svalid[32];
        __shared__ unsigned int srem[32];
        for (int c = w; c < 32; c += BLK / 32) {
            int idx = c * 32 + lane;
            int v = (idx < TOPK) ? g_val[idx] : 0;
            unsigned int b = __ballot_sync(0xFFFFFFFFu, v != 0);
            if (lane == 0) svalid[c] = b;
        }
        __syncthreads();

        if (t < 32) {
            unsigned int rem = 0;
            unsigned int nz = g_nzchunks;    // uniform across lanes
            while (nz) {
                int c = __ffs(nz) - 1;       // ascending chunk order
                nz &= nz - 1;
                unsigned int m[32];
                #pragma unroll
                for (int k = 0; k < 32; k++) {
                    unsigned int mm = g_mask[(c * 32 + k) * 32 + lane];
                    unsigned int vmask;
                    if (lane > c)       vmask = 0xFFFFFFFFu;
                    else if (lane < c)  vmask = 0u;
                    else                vmask = (k == 31) ? 0u : (0xFFFFFFFFu << (k + 1));
                    m[k] = mm & vmask;
                }
                unsigned int vb = svalid[c];
                unsigned int myrem = rem;
                unsigned int kb = 0;
                #pragma unroll
                for (int k2 = 0; k2 < 32; k2++) {
                    unsigned int kept = ((vb >> k2) & 1u) & ((~(myrem >> k2)) & 1u);
                    kb |= kept << k2;
                    myrem |= (0u - kept) & m[k2];
                }
                unsigned int keptbits = __shfl_sync(0xFFFFFFFFu, kb, c);
                #pragma unroll
                for (int k2 = 0; k2 < 32; k2++)
                    rem |= (0u - ((keptbits >> k2) & 1u)) & m[k2];
            }
            srem[lane] = rem;
        }
        __syncthreads();

        // outputs: [boxes 1000*4 | scores 1000 | kpss 1000*10] = 15000 floats
        for (int r = t; r < TOPK; r += BLK) {
            unsigned int rw = srem[r >> 5];
            int keep = g_val[r] && !((rw >> (r & 31)) & 1u);
            float m = keep ? 1.0f : 0.0f;
            float4 b = g_bx4[r];
            out[r * 4 + 0] = m * b.x;
            out[r * 4 + 1] = m * b.y;
            out[r * 4 + 2] = m * b.z;
            out[r * 4 + 3] = m * b.w;
            out[4000 + r] = m * g_sc[r];
            #pragma unroll
            for (int c = 0; c < 10; c++)
                out[5000 + r * 10 + c] = m * g_kp[r * 10 + c];
        }
    }
}

// ---------------- launcher: 2 graph nodes ----------------
extern "C" void kernel_launch(void* const* d_in, const int* in_sizes, int n_in,
                              void* d_out, int out_size) {
    // metadata order: x, scores8, bbox8, kps8, scores16, bbox16, kps16, scores32, bbox32, kps32
    const float* s8  = (const float*)d_in[1];
    const float* b8  = (const float*)d_in[2];
    const float* k8  = (const float*)d_in[3];
    const float* s16 = (const float*)d_in[4];
    const float* b16 = (const float*)d_in[5];
    const float* k16 = (const float*)d_in[6];
    const float* s32 = (const float*)d_in[7];
    const float* b32 = (const float*)d_in[8];
    const float* k32 = (const float*)d_in[9];
    float* out = (float*)d_out;

    k_front<<<GRID1, BLK>>>(s8, s16, s32);
    k_rest<<<GRID2, BLK>>>(s8, s16, s32, b8, k8, b16, k16, b32, k32, out);
}

// round 12
// speedup vs baseline: 2.7722x; 1.2978x over previous
#include <cuda_runtime.h>
#include <math.h>

// ---------------- problem constants ----------------
#define N8   130560   // (2176/8)*(3840/8)
#define N16  32640
#define N32  8160
#define NT   (N8 + N16 + N32)   // 171360
#define N8_4  (N8 / 4)
#define N16_4 (N16 / 4)
#define NT4   (NT / 4)
#define FW8  480
#define FW16 240
#define FW32 120
#define TOPK 1000
#define NCAND 4096
#define NBINS 4096
#define HICAP 16384
#define NMS_T 0.4f

#define GRID1 148
#define BLK   512
#define NTH1  (GRID1 * BLK)
#define GRID2 148
#define NTH2  (GRID2 * BLK)      // 75776
#define NW2   (NTH2 / 32)        // 2368

#define BIN_BASE    0x1FC00u     // 0x3F800000 >> 13  (raw == 1.0f)
#define COARSE_BITS 0x40000000u  // raw == 2.0f

// ---------------- device scratch (no allocations allowed) ----------------
__device__ unsigned int        g_hist[NBINS];     // zero at load; re-zeroed every run
__device__ unsigned int        g_hicount;         // zero at load; reset every run
__device__ unsigned long long  g_hi[HICAP];
__device__ unsigned int        g_ccount;          // zero at load; reset every run
__device__ unsigned long long  g_cand[NCAND];
__device__ float4              g_bx4[1024];
__device__ float               g_sc[1024];
__device__ float               g_kp[1024 * 10];
__device__ int                 g_val[1024];
__device__ unsigned int        g_mask[1024 * 32];
__device__ unsigned int        g_nzchunks;
// software barriers (generation/count based; self-resetting across replays)
__device__ unsigned int           g_bar_count;
__device__ volatile unsigned int  g_bar_gen;
__device__ unsigned int           g_done;

__device__ __forceinline__ void grid_sync2() {   // GRID2-wide
    __syncthreads();
    if (threadIdx.x == 0) {
        __threadfence();
        unsigned int gen = g_bar_gen;
        if (atomicAdd(&g_bar_count, 1u) == GRID2 - 1) {
            g_bar_count = 0;
            __threadfence();
            g_bar_gen = gen + 1;
        } else {
            while (g_bar_gen == gen) { }
        }
        __threadfence();
    }
    __syncthreads();
}

// spread bin for bits >= 1.0f: bins 1..4095;  bin 0 = positives below 1.0f
__device__ __forceinline__ unsigned int hi_bin(unsigned int bits) {
    return min(4095u, (bits >> 13) - BIN_BASE + 1u);
}

// ================= K1: histogram (de-contended) + coarse candidate store =================
__global__ __launch_bounds__(BLK)
void k_front(const float* __restrict__ s8, const float* __restrict__ s16,
             const float* __restrict__ s32) {
    const int tid = blockIdx.x * BLK + threadIdx.x;
    for (int v = tid; v < NT4; v += NTH1) {
        float4 r;
        if (v < N8_4)               r = reinterpret_cast<const float4*>(s8)[v];
        else if (v < N8_4 + N16_4)  r = reinterpret_cast<const float4*>(s16)[v - N8_4];
        else                        r = reinterpret_cast<const float4*>(s32)[v - N8_4 - N16_4];
        float ra[4] = {r.x, r.y, r.z, r.w};
        unsigned int base = (unsigned int)v * 4u;
        int c0 = 0;   // positives below 1.0 (bin-0 aggregate)
        #pragma unroll
        for (int c = 0; c < 4; c++) {
            float raw = ra[c];
            if (raw >= 1.0f) {
                unsigned int bits = __float_as_uint(raw);
                atomicAdd(&g_hist[hi_bin(bits)], 1u);
                if (bits >= COARSE_BITS) {
                    unsigned int pos = atomicAdd(&g_hicount, 1u);
                    if (pos < HICAP)
                        g_hi[pos] = ((unsigned long long)bits << 32) |
                                    (unsigned long long)(0xFFFFFFFFu - (base + c));
                }
            } else if (raw > 0.0f) {
                c0++;
            }
        }
        // warp-aggregated bin-0 update (converged active lanes)
        unsigned int act = __activemask();
        int tot = c0;
        #pragma unroll
        for (int d = 16; d > 0; d >>= 1) tot += __shfl_xor_sync(act, tot, d);
        if ((threadIdx.x & 31) == (unsigned)(__ffs(act) - 1) && tot > 0)
            atomicAdd(&g_hist[0], (unsigned int)tot);
    }
}

// ===== K2 (148 blocks): kmin -> compact -> rank+decode -> mask -> reduce -> out =====
__global__ __launch_bounds__(BLK)
void k_rest(const float* __restrict__ s8,  const float* __restrict__ s16, const float* __restrict__ s32,
            const float* __restrict__ b8,  const float* __restrict__ k8,
            const float* __restrict__ b16, const float* __restrict__ k16,
            const float* __restrict__ b32, const float* __restrict__ k32,
            float* __restrict__ out) {
    const int tid  = blockIdx.x * BLK + threadIdx.x;
    const int t    = threadIdx.x;
    const int lane = t & 31;
    const int w    = t >> 5;

    __shared__ unsigned long long scand[NCAND];   // 32 KB candidate stage
    __shared__ float4             sbx[1024];      // 16 KB box stage

    // ---- B: per-block redundant boundary-bin search ----
    __shared__ unsigned int sw_tot[BLK / 32];
    __shared__ unsigned int skmin;
    unsigned int kmin;
    {
        unsigned int loc[8];
        unsigned int p = 0;
        #pragma unroll
        for (int b = 0; b < 8; b++) { loc[b] = g_hist[t * 8 + b]; p += loc[b]; }
        unsigned int s = p;   // warp suffix-sum over lanes >= lane
        #pragma unroll
        for (int d = 1; d < 32; d <<= 1) {
            unsigned int o = __shfl_down_sync(0xFFFFFFFFu, s, d);
            if (lane + d < 32) s += o;
        }
        unsigned int wtot = __shfl_sync(0xFFFFFFFFu, s, 0);
        if (lane == 0) sw_tot[w] = wtot;
        __syncthreads();
        unsigned int tail = 0;
        #pragma unroll
        for (int ww = 0; ww < BLK / 32; ww++) tail += (ww > w) ? sw_tot[ww] : 0u;
        unsigned int suffix = s + tail;     // sum of bins [t*8 .. NBINS)
        unsigned int nxt = suffix - p;
        if (suffix >= TOPK && nxt < TOPK) {
            unsigned int running = nxt;
            int B = t * 8;
            #pragma unroll
            for (int b = 7; b >= 0; b--) {
                running += loc[b];
                if (running >= TOPK) { B = t * 8 + b; break; }
            }
            skmin = (B == 0) ? 1u : ((BIN_BASE + (unsigned int)B - 1u) << 13);
        }
        if (t == 0 && suffix < TOPK) skmin = 1u;   // fewer than TOPK valid overall
        __syncthreads();
        kmin = skmin;
    }

    // ---- C: collect candidates >= kmin ----
    unsigned int hic = g_hicount;
    bool fallback = (kmin < COARSE_BITS) || (hic > HICAP);
    if (!fallback) {
        for (unsigned int e = tid; e < hic; e += NTH2) {
            unsigned long long pk = g_hi[e];
            if ((unsigned int)(pk >> 32) >= kmin) {
                unsigned int pos = atomicAdd(&g_ccount, 1u);
                if (pos < NCAND) g_cand[pos] = pk;
            }
        }
    } else {
        for (int v = tid; v < NT4; v += NTH2) {
            float4 r;
            if (v < N8_4)               r = reinterpret_cast<const float4*>(s8)[v];
            else if (v < N8_4 + N16_4)  r = reinterpret_cast<const float4*>(s16)[v - N8_4];
            else                        r = reinterpret_cast<const float4*>(s32)[v - N8_4 - N16_4];
            float  ra[4] = {r.x, r.y, r.z, r.w};
            unsigned int base = (unsigned int)v * 4u;
            #pragma unroll
            for (int c = 0; c < 4; c++) {
                if (ra[c] > 0.0f) {
                    unsigned int bits = __float_as_uint(ra[c]);
                    if (bits >= kmin) {
                        unsigned int pos = atomicAdd(&g_ccount, 1u);
                        if (pos < NCAND)
                            g_cand[pos] = ((unsigned long long)bits << 32) |
                                          (unsigned long long)(0xFFFFFFFFu - (base + c));
                    }
                }
            }
        }
    }
    grid_sync2();

    // ---- DE: stage candidates in smem; warp-per-candidate rank + decode ----
    {
        unsigned int C = g_ccount;
        if (C > NCAND) C = NCAND;

        for (unsigned int i = t; i < C; i += BLK) scand[i] = g_cand[i];

        // housekeeping for next replay / this run
        for (int i = tid; i < NBINS; i += NTH2) g_hist[i] = 0;
        if (tid == 0) { g_hicount = 0; g_nzchunks = 0u; }

        // zero never-written rank rows [C, 1024)
        if (tid >= (int)C && tid < 1024) {
            g_val[tid] = 0;
            g_sc[tid] = 0.0f;
            g_bx4[tid] = make_float4(0.0f, 0.0f, 0.0f, 0.0f);
            #pragma unroll
            for (int c = 0; c < 10; c++) g_kp[tid * 10 + c] = 0.0f;
        }
        __syncthreads();

        int gw = tid >> 5;
        for (int cand = gw; cand < (int)C; cand += NW2) {
            unsigned long long mine = scand[cand];
            int cnt = 0;
            for (int i = lane; i < (int)C; i += 32) cnt += (scand[i] > mine) ? 1 : 0;
            int rank = __reduce_add_sync(0xFFFFFFFFu, cnt);
            if (rank < TOPK && lane == 0) {
                unsigned int bits = (unsigned int)(mine >> 32);
                float raw = __uint_as_float(bits);
                int idx = (int)(0xFFFFFFFFu - (unsigned int)(mine & 0xFFFFFFFFu));
                int li, fw;
                float stride;
                const float* bb;
                const float* kp;
                if (idx < N8)            { li = idx;            stride = 8.0f;  fw = FW8;  bb = b8;  kp = k8;  }
                else if (idx < N8 + N16) { li = idx - N8;       stride = 16.0f; fw = FW16; bb = b16; kp = k16; }
                else                     { li = idx - N8 - N16; stride = 32.0f; fw = FW32; bb = b32; kp = k32; }
                float cx = (float)(li % fw) * stride;
                float cy = (float)(li / fw) * stride;
                float4 d = reinterpret_cast<const float4*>(bb)[li];
                g_bx4[rank] = make_float4(cx - d.x * stride, cy - d.y * stride,
                                          cx + d.z * stride, cy + d.w * stride);
                const float2* kk2 = reinterpret_cast<const float2*>(kp) + (size_t)li * 5;
                #pragma unroll
                for (int j = 0; j < 5; j++) {
                    float2 kv = kk2[j];
                    g_kp[rank * 10 + 2 * j]     = kv.x * stride + cx;
                    g_kp[rank * 10 + 2 * j + 1] = kv.y * stride + cy;
                }
                g_sc[rank] = 1.0f / (1.0f + expf(-raw));
                g_val[rank] = 1;
            }
        }
    }
    grid_sync2();

    // ---- F: stage boxes in smem; upper-triangle suppression bitmask ----
    if (tid == 0) g_ccount = 0;   // consumed; reset for next replay
    {
        for (int i = t; i < 1024; i += BLK) sbx[i] = g_bx4[i];
        __syncthreads();

        int gw = tid >> 5;
        for (int task = gw; task < TOPK * 32; task += NW2) {
            int i  = task >> 5;
            int wj = task & 31;
            if (wj * 32 + 31 <= i) continue;    // word entirely j <= i: G masks it
            float4 bi = sbx[i];
            int j = wj * 32 + lane;
            float4 bj = sbx[j];
            bool bit = false;
            if (j < TOPK && j > i) {
                float iar = (bi.z - bi.x) * (bi.w - bi.y);
                float jar = (bj.z - bj.x) * (bj.w - bj.y);
                float ww2 = fmaxf(fminf(bi.z, bj.z) - fmaxf(bi.x, bj.x), 0.0f);
                float hh2 = fmaxf(fminf(bi.w, bj.w) - fmaxf(bi.y, bj.y), 0.0f);
                float inter = ww2 * hh2;
                float uni = fmaxf(iar + jar - inter, 1e-9f);
                bit = inter > NMS_T * uni;
            }
            unsigned int b = __ballot_sync(0xFFFFFFFFu, bit);
            if (lane == 0) {
                g_mask[i * 32 + wj] = b;
                if (b) atomicOr(&g_nzchunks, 1u << (i >> 5));
            }
        }
    }

    // ---- arrive-and-exit: only block 0 proceeds to G ----
    __syncthreads();
    if (threadIdx.x == 0) { __threadfence(); atomicAdd(&g_done, 1u); }
    if (blockIdx.x != 0) return;
    if (threadIdx.x == 0) {
        while (*(volatile unsigned int*)&g_done != GRID2) { }
        g_done = 0;
        __threadfence();
    }
    __syncthreads();

    // ---- G: greedy reduce over nonzero chunks + outputs (block 0 only) ----
    {
        __shared__ unsigned int svalid[32];
        __shared__ unsigned int srem[32];
        for (int c = w; c < 32; c += BLK / 32) {
            int idx = c * 32 + lane;
            int v = (idx < TOPK) ? g_val[idx] : 0;
            unsigned int b = __ballot_sync(0xFFFFFFFFu, v != 0);
            if (lane == 0) svalid[c] = b;
        }
        __syncthreads();

        if (t < 32) {
            unsigned int rem = 0;
            unsigned int nz = g_nzchunks;    // uniform across lanes
            while (nz) {
                int c = __ffs(nz) - 1;       // ascending chunk order
                nz &= nz - 1;
                unsigned int m[32];
                #pragma unroll
                for (int k = 0; k < 32; k++) {
                    unsigned int mm = g_mask[(c * 32 + k) * 32 + lane];
                    unsigned int vmask;
                    if (lane > c)       vmask = 0xFFFFFFFFu;
                    else if (lane < c)  vmask = 0u;
                    else                vmask = (k == 31) ? 0u : (0xFFFFFFFFu << (k + 1));
                    m[k] = mm & vmask;
                }
                unsigned int vb = svalid[c];
                unsigned int myrem = rem;
                unsigned int kb = 0;
                #pragma unroll
                for (int k2 = 0; k2 < 32; k2++) {
                    unsigned int kept = ((vb >> k2) & 1u) & ((~(myrem >> k2)) & 1u);
                    kb |= kept << k2;
                    myrem |= (0u - kept) & m[k2];
                }
                unsigned int keptbits = __shfl_sync(0xFFFFFFFFu, kb, c);
                #pragma unroll
                for (int k2 = 0; k2 < 32; k2++)
                    rem |= (0u - ((keptbits >> k2) & 1u)) & m[k2];
            }
            srem[lane] = rem;
        }
        __syncthreads();

        // outputs: [boxes 1000*4 | scores 1000 | kpss 1000*10] = 15000 floats
        for (int r = t; r < TOPK; r += BLK) {
            unsigned int rw = srem[r >> 5];
            int keep = g_val[r] && !((rw >> (r & 31)) & 1u);
            float m = keep ? 1.0f : 0.0f;
            float4 b = g_bx4[r];
            out[r * 4 + 0] = m * b.x;
            out[r * 4 + 1] = m * b.y;
            out[r * 4 + 2] = m * b.z;
            out[r * 4 + 3] = m * b.w;
            out[4000 + r] = m * g_sc[r];
            #pragma unroll
            for (int c = 0; c < 10; c++)
                out[5000 + r * 10 + c] = m * g_kp[r * 10 + c];
        }
    }
}

// ---------------- launcher: 2 graph nodes ----------------
extern "C" void kernel_launch(void* const* d_in, const int* in_sizes, int n_in,
                              void* d_out, int out_size) {
    // metadata order: x, scores8, bbox8, kps8, scores16, bbox16, kps16, scores32, bbox32, kps32
    const float* s8  = (const float*)d_in[1];
    const float* b8  = (const float*)d_in[2];
    const float* k8  = (const float*)d_in[3];
    const float* s16 = (const float*)d_in[4];
    const float* b16 = (const float*)d_in[5];
    const float* k16 = (const float*)d_in[6];
    const float* s32 = (const float*)d_in[7];
    const float* b32 = (const float*)d_in[8];
    const float* k32 = (const float*)d_in[9];
    float* out = (float*)d_out;

    k_front<<<GRID1, BLK>>>(s8, s16, s32);
    k_rest<<<GRID2, BLK>>>(s8, s16, s32, b8, k8, b16, k16, b32, k32, out);
}